// round 1
// baseline (speedup 1.0000x reference)
#include <cuda_runtime.h>
#include <cuda_bf16.h>
#include <cstddef>

// YOLOv3 decode: out[B,255,H,W] -> rows[(b,h,w,a), 6] + mask
// row = [sigmoid(o0), (w+o1)*t/case, (h+o2)*t/case,
//        A[a].x*exp(o3)/case, A[a].y*exp(o4)/case, argmax(o5..o84)]
// mask = o0 > thresh (pre-sigmoid), stored as 1.0f/0.0f.

__global__ void decode_scale_kernel(const float* __restrict__ in,
                                    const float* __restrict__ anchors,
                                    const float* __restrict__ threshp,
                                    const int*   __restrict__ casep,
                                    float* __restrict__ boxes,   // already offset for this scale
                                    float* __restrict__ mask,    // already offset for this scale
                                    int B, int H, int W, float t)
{
    const int idx   = blockIdx.x * blockDim.x + threadIdx.x;
    const int total = B * H * W * 3;
    if (idx >= total) return;

    const int a  = idx % 3;
    const int w  = (idx / 3) % W;
    const int bh = idx / (3 * W);
    const int h  = bh % H;
    const int b  = bh / H;

    const int cs = H * W;  // channel stride
    const float* p = in + ((size_t)(b * 255 + a * 85) * cs + (size_t)h * W + w);

    const float o0 = __ldg(p);
    const float o1 = __ldg(p + (size_t)cs);
    const float o2 = __ldg(p + 2 * (size_t)cs);
    const float o3 = __ldg(p + 3 * (size_t)cs);
    const float o4 = __ldg(p + 4 * (size_t)cs);

    // argmax over 80 class logits; strict '>' keeps the FIRST max (jnp.argmax tie rule)
    float maxv = __ldg(p + 5 * (size_t)cs);
    int   cls  = 0;
    #pragma unroll 8
    for (int d = 1; d < 80; ++d) {
        float v = __ldg(p + (size_t)(5 + d) * cs);
        if (v > maxv) { maxv = v; cls = d; }
    }

    // 'case' scalar may arrive as int32 (416) or float32 (416.0f); decode bit pattern.
    const int iv = __ldg(casep);
    const float case_f = (iv > 0 && iv < 1000000) ? (float)iv : __int_as_float(iv);
    const float inv_case = 1.0f / case_f;
    const float scale = t * inv_case;

    const float prob = 1.0f / (1.0f + expf(-o0));
    const float cx = ((float)w + o1) * scale;
    const float cy = ((float)h + o2) * scale;
    const float bw = __ldg(anchors + a * 2 + 0) * expf(o3) * inv_case;
    const float bhh = __ldg(anchors + a * 2 + 1) * expf(o4) * inv_case;

    float* r = boxes + (size_t)idx * 6;
    r[0] = prob;
    r[1] = cx;
    r[2] = cy;
    r[3] = bw;
    r[4] = bhh;
    r[5] = (float)cls;

    mask[idx] = (o0 > __ldg(threshp)) ? 1.0f : 0.0f;
}

extern "C" void kernel_launch(void* const* d_in, const int* in_sizes, int n_in,
                              void* d_out, int out_size)
{
    const float* o13 = (const float*)d_in[0];
    const float* o26 = (const float*)d_in[1];
    const float* o52 = (const float*)d_in[2];
    const float* a13 = (const float*)d_in[3];
    const float* a26 = (const float*)d_in[4];
    const float* a52 = (const float*)d_in[5];
    const float* th  = (const float*)d_in[6];
    const int*   cs  = (const int*)  d_in[7];

    // Derive B from sizes (shape per scale: [B, 255, S, S])
    const int B = in_sizes[0] / (255 * 13 * 13);

    const int N13 = B * 13 * 13 * 3;
    const int N26 = B * 26 * 26 * 3;
    const int N52 = B * 52 * 52 * 3;
    const int N   = N13 + N26 + N52;

    float* boxes = (float*)d_out;              // [N, 6]
    float* mask  = (float*)d_out + (size_t)N * 6;  // [N] as 0/1 floats

    const int TPB = 256;
    decode_scale_kernel<<<(N13 + TPB - 1) / TPB, TPB>>>(
        o13, a13, th, cs, boxes, mask, B, 13, 13, 32.0f);
    decode_scale_kernel<<<(N26 + TPB - 1) / TPB, TPB>>>(
        o26, a26, th, cs, boxes + (size_t)N13 * 6, mask + N13, B, 26, 26, 16.0f);
    decode_scale_kernel<<<(N52 + TPB - 1) / TPB, TPB>>>(
        o52, a52, th, cs, boxes + (size_t)(N13 + N26) * 6, mask + N13 + N26, B, 52, 52, 8.0f);
}

// round 2
// speedup vs baseline: 1.1524x; 1.1524x over previous
#include <cuda_runtime.h>
#include <cuda_bf16.h>
#include <cstddef>

// Fused YOLOv3 decode, all 3 scales in ONE kernel.
// Parallelization: one thread per grid CELL (b,h,w); the thread handles all
// 3 anchors. Warp lanes then access 32 consecutive floats on every channel
// load -> perfectly coalesced (4 sectors / warp-load).
// Argmax loads are batched 16-wide for MLP.

__global__ __launch_bounds__(256)
void yolo_decode_fused(const float* __restrict__ o13,
                       const float* __restrict__ o26,
                       const float* __restrict__ o52,
                       const float* __restrict__ a13,
                       const float* __restrict__ a26,
                       const float* __restrict__ a52,
                       const float* __restrict__ threshp,
                       const int*   __restrict__ casep,
                       float* __restrict__ boxes,   // [N,6]
                       float* __restrict__ mask,    // [N]
                       int B)
{
    const int c = blockIdx.x * blockDim.x + threadIdx.x;

    const int C13 = B * 13 * 13;
    const int C26 = B * 26 * 26;
    const int C52 = B * 52 * 52;
    if (c >= C13 + C26 + C52) return;

    // Resolve scale
    const float* in; const float* anch;
    int S, local, rowoff; float t;
    if (c < C13)             { in = o13; anch = a13; S = 13; local = c;             rowoff = 0;               t = 32.0f; }
    else if (c < C13 + C26)  { in = o26; anch = a26; S = 26; local = c - C13;       rowoff = C13 * 3;         t = 16.0f; }
    else                     { in = o52; anch = a52; S = 52; local = c - C13 - C26; rowoff = (C13 + C26) * 3; t = 8.0f;  }

    const int HW  = S * S;
    const int b   = local / HW;
    const int pos = local - b * HW;
    const int h   = pos / S;
    const int w   = pos - h * S;

    // 'case' scalar: int 416 or float 416.0f
    const int iv = __ldg(casep);
    const float case_f = (iv > 0 && iv < 1000000) ? (float)iv : __int_as_float(iv);
    const float inv_case = 1.0f / case_f;
    const float scale = t * inv_case;
    const float thresh = __ldg(threshp);

    const float* base = in + (size_t)b * 255 * HW + pos;

    #pragma unroll
    for (int a = 0; a < 3; ++a) {
        const float* p = base + (size_t)(a * 85) * HW;

        float o0 = __ldg(p);
        float o1 = __ldg(p + (size_t)HW);
        float o2 = __ldg(p + 2 * (size_t)HW);
        float o3 = __ldg(p + 3 * (size_t)HW);
        float o4 = __ldg(p + 4 * (size_t)HW);

        // Argmax over 80 class logits, 16-wide load batches (MLP=16).
        // Strict '>' keeps FIRST max (jnp.argmax tie rule).
        float maxv = -3.4e38f;
        int   cls  = 0;
        #pragma unroll
        for (int d0 = 0; d0 < 80; d0 += 16) {
            float v[16];
            #pragma unroll
            for (int i = 0; i < 16; ++i)
                v[i] = __ldg(p + (size_t)(5 + d0 + i) * HW);
            #pragma unroll
            for (int i = 0; i < 16; ++i)
                if (v[i] > maxv) { maxv = v[i]; cls = d0 + i; }
        }

        const float prob = 1.0f / (1.0f + expf(-o0));
        const float cx = ((float)w + o1) * scale;
        const float cy = ((float)h + o2) * scale;
        const float bw = __ldg(anch + a * 2 + 0) * expf(o3) * inv_case;
        const float bh = __ldg(anch + a * 2 + 1) * expf(o4) * inv_case;

        const int row = rowoff + local * 3 + a;
        float* r = boxes + (size_t)row * 6;
        r[0] = prob;
        r[1] = cx;
        r[2] = cy;
        r[3] = bw;
        r[4] = bh;
        r[5] = (float)cls;

        mask[row] = (o0 > thresh) ? 1.0f : 0.0f;
    }
}

extern "C" void kernel_launch(void* const* d_in, const int* in_sizes, int n_in,
                              void* d_out, int out_size)
{
    const float* o13 = (const float*)d_in[0];
    const float* o26 = (const float*)d_in[1];
    const float* o52 = (const float*)d_in[2];
    const float* a13 = (const float*)d_in[3];
    const float* a26 = (const float*)d_in[4];
    const float* a52 = (const float*)d_in[5];
    const float* th  = (const float*)d_in[6];
    const int*   cs  = (const int*)  d_in[7];

    const int B = in_sizes[0] / (255 * 13 * 13);

    const int C13 = B * 13 * 13;
    const int C26 = B * 26 * 26;
    const int C52 = B * 52 * 52;
    const int cells = C13 + C26 + C52;
    const int N = cells * 3;

    float* boxes = (float*)d_out;                   // [N,6]
    float* mask  = (float*)d_out + (size_t)N * 6;   // [N]

    const int TPB = 256;
    yolo_decode_fused<<<(cells + TPB - 1) / TPB, TPB>>>(
        o13, o26, o52, a13, a26, a52, th, cs, boxes, mask, B);
}

// round 3
// speedup vs baseline: 1.4646x; 1.2709x over previous
#include <cuda_runtime.h>
#include <cuda_bf16.h>
#include <cstddef>

// Fused YOLOv3 decode, all 3 scales, one kernel.
// One thread per (anchor, cell), with anchor as the OUTER index:
//   tid = a * cells + cell
// Warp lanes cover consecutive cells (consecutive w) -> every channel load is
// perfectly coalesced; one anchor per thread keeps regs low -> high occupancy.
// Argmax class loads batched 16-wide for MLP.

__global__ __launch_bounds__(256)
void yolo_decode_fused(const float* __restrict__ o13,
                       const float* __restrict__ o26,
                       const float* __restrict__ o52,
                       const float* __restrict__ a13,
                       const float* __restrict__ a26,
                       const float* __restrict__ a52,
                       const float* __restrict__ threshp,
                       const int*   __restrict__ casep,
                       float* __restrict__ boxes,   // [N,6]
                       float* __restrict__ mask,    // [N]
                       int B, int cells)
{
    const int tid = blockIdx.x * blockDim.x + threadIdx.x;
    if (tid >= 3 * cells) return;

    const int a    = tid / cells;       // anchor 0..2
    const int cell = tid - a * cells;   // global cell id

    const int C13 = B * 13 * 13;
    const int C26 = B * 26 * 26;

    // Resolve scale from cell id
    const float* in; const float* anch;
    int S, local, rowoff; float t;
    if (cell < C13)            { in = o13; anch = a13; S = 13; local = cell;              rowoff = 0;               t = 32.0f; }
    else if (cell < C13 + C26) { in = o26; anch = a26; S = 26; local = cell - C13;        rowoff = C13 * 3;         t = 16.0f; }
    else                       { in = o52; anch = a52; S = 52; local = cell - C13 - C26;  rowoff = (C13 + C26) * 3; t = 8.0f;  }

    const int HW  = S * S;
    const int b   = local / HW;
    const int pos = local - b * HW;
    const int h   = pos / S;
    const int w   = pos - h * S;

    // 'case' scalar: int 416 or float 416.0f (dtype-robust)
    const int iv = __ldg(casep);
    const float case_f = (iv > 0 && iv < 1000000) ? (float)iv : __int_as_float(iv);
    const float inv_case = 1.0f / case_f;
    const float scale = t * inv_case;
    const float thresh = __ldg(threshp);

    // base of this (b, anchor) 85-channel slab at this spatial position
    const float* p = in + (size_t)(b * 255 + a * 85) * HW + pos;

    const float o0 = __ldg(p);
    const float o1 = __ldg(p + HW);
    const float o2 = __ldg(p + 2 * HW);
    const float o3 = __ldg(p + 3 * HW);
    const float o4 = __ldg(p + 4 * HW);

    // Argmax over 80 class logits, 16-wide load batches (MLP=16).
    // Strict '>' keeps FIRST max (jnp.argmax tie rule).
    float maxv = -3.4e38f;
    int   cls  = 0;
    #pragma unroll
    for (int d0 = 0; d0 < 80; d0 += 16) {
        float v[16];
        #pragma unroll
        for (int i = 0; i < 16; ++i)
            v[i] = __ldg(p + (5 + d0 + i) * HW);
        #pragma unroll
        for (int i = 0; i < 16; ++i)
            if (v[i] > maxv) { maxv = v[i]; cls = d0 + i; }
    }

    const float prob = 1.0f / (1.0f + expf(-o0));
    const float cx = ((float)w + o1) * scale;
    const float cy = ((float)h + o2) * scale;
    const float bw = __ldg(anch + a * 2 + 0) * expf(o3) * inv_case;
    const float bh = __ldg(anch + a * 2 + 1) * expf(o4) * inv_case;

    const int row = rowoff + local * 3 + a;
    float* r = boxes + (size_t)row * 6;
    r[0] = prob;
    r[1] = cx;
    r[2] = cy;
    r[3] = bw;
    r[4] = bh;
    r[5] = (float)cls;

    mask[row] = (o0 > thresh) ? 1.0f : 0.0f;
}

extern "C" void kernel_launch(void* const* d_in, const int* in_sizes, int n_in,
                              void* d_out, int out_size)
{
    const float* o13 = (const float*)d_in[0];
    const float* o26 = (const float*)d_in[1];
    const float* o52 = (const float*)d_in[2];
    const float* a13 = (const float*)d_in[3];
    const float* a26 = (const float*)d_in[4];
    const float* a52 = (const float*)d_in[5];
    const float* th  = (const float*)d_in[6];
    const int*   cs  = (const int*)  d_in[7];

    const int B = in_sizes[0] / (255 * 13 * 13);

    const int C13 = B * 13 * 13;
    const int C26 = B * 26 * 26;
    const int C52 = B * 52 * 52;
    const int cells = C13 + C26 + C52;
    const int N = cells * 3;

    float* boxes = (float*)d_out;                   // [N,6]
    float* mask  = (float*)d_out + (size_t)N * 6;   // [N]

    const int TPB = 256;
    const int threads = 3 * cells;
    yolo_decode_fused<<<(threads + TPB - 1) / TPB, TPB>>>(
        o13, o26, o52, a13, a26, a52, th, cs, boxes, mask, B, cells);
}